// round 1
// baseline (speedup 1.0000x reference)
#include <cuda_runtime.h>
#include <cuda_bf16.h>

#define NMAX 100000
#define EMAX 3300000   // E + N self loops
#define FIN 512
#define HD  64
#define NITER 10
#define ALPHAF 0.1f

// ---------------- scratch (device globals; no allocation allowed) ------------
__device__ float g_h[NMAX * HD];        // MLP output (teleport term)
__device__ float g_z0[NMAX * HD];       // ping
__device__ float g_z1[NMAX * HD];       // pong
__device__ float g_deg[NMAX];           // degree -> dinv (in place)
__device__ int   g_cnt[NMAX];           // in-degree histogram (by col)
__device__ int   g_rowptr[NMAX + 1];    // CSR row pointer (by destination)
__device__ int   g_cursor[NMAX];        // scatter cursors
__device__ int   g_src[EMAX];           // CSR: source node per edge
__device__ float g_w[EMAX];             // CSR: normalized weight per edge

// ---------------- preprocessing kernels --------------------------------------

__global__ void zero_kernel(int N) {
    int i = blockIdx.x * blockDim.x + threadIdx.x;
    int stride = gridDim.x * blockDim.x;
    for (; i < N; i += stride) { g_deg[i] = 0.0f; g_cnt[i] = 0; }
}

// degrees by row (source), in-degree counts by col (destination). Edges [0,E)
// come from edge_index; edges [E, E+N) are self loops with weight 1.
__global__ void degcnt_kernel(const int* __restrict__ ei,
                              const float* __restrict__ ew, int E, int N) {
    int total = E + N;
    int i = blockIdx.x * blockDim.x + threadIdx.x;
    int stride = gridDim.x * blockDim.x;
    for (; i < total; i += stride) {
        int r, c; float w;
        if (i < E) { r = ei[i]; c = ei[E + i]; w = ew[i]; }
        else       { r = c = i - E; w = 1.0f; }
        atomicAdd(&g_deg[r], w);
        atomicAdd(&g_cnt[c], 1);
    }
}

__global__ void dinv_kernel(int N) {
    int i = blockIdx.x * blockDim.x + threadIdx.x;
    int stride = gridDim.x * blockDim.x;
    for (; i < N; i += stride) {
        float d = g_deg[i];
        g_deg[i] = (d > 0.0f) ? rsqrtf(d) : 0.0f;
    }
}

// single-block exclusive scan of g_cnt -> g_rowptr (and cursor copy)
__global__ void scan_kernel(int N, int total) {
    __shared__ int sdata[1024];
    __shared__ int carry;
    int tid = threadIdx.x;
    if (tid == 0) carry = 0;
    __syncthreads();
    for (int base = 0; base < N; base += 1024) {
        int i = base + tid;
        int v = (i < N) ? g_cnt[i] : 0;
        sdata[tid] = v;
        __syncthreads();
        #pragma unroll
        for (int off = 1; off < 1024; off <<= 1) {
            int t = (tid >= off) ? sdata[tid - off] : 0;
            __syncthreads();
            sdata[tid] += t;
            __syncthreads();
        }
        int cbase = carry;
        int excl = sdata[tid] - v + cbase;
        if (i < N) { g_rowptr[i] = excl; g_cursor[i] = excl; }
        __syncthreads();
        if (tid == 1023) carry = cbase + sdata[1023];
        __syncthreads();
    }
    if (tid == 0) g_rowptr[N] = total;
}

__global__ void scatter_kernel(const int* __restrict__ ei,
                               const float* __restrict__ ew, int E, int N) {
    int total = E + N;
    int i = blockIdx.x * blockDim.x + threadIdx.x;
    int stride = gridDim.x * blockDim.x;
    for (; i < total; i += stride) {
        int r, c; float w;
        if (i < E) { r = ei[i]; c = ei[E + i]; w = ew[i]; }
        else       { r = c = i - E; w = 1.0f; }
        float wn = g_deg[r] * w * g_deg[c];   // g_deg holds dinv now
        int pos = atomicAdd(&g_cursor[c], 1);
        g_src[pos] = r;
        g_w[pos]   = wn;
    }
}

// ---------------- MLP: h = relu(x@W0+b0)@W1+b1, also seeds z0=h --------------
// block = 256 threads, tile = 64 rows x 64 cols, 4x4 micro-tile per thread.
__global__ __launch_bounds__(256) void mlp_kernel(
    const float* __restrict__ x,  const float* __restrict__ W0,
    const float* __restrict__ b0, const float* __restrict__ W1,
    const float* __restrict__ b1, int N)
{
    __shared__ float As[64][17];
    __shared__ float Bs[16][64];
    __shared__ float Ts[64][65];
    __shared__ float W1s[64][64];
    __shared__ float b0s[64];
    __shared__ float b1s[64];

    int tid = threadIdx.x;
    int tx = tid & 15, ty = tid >> 4;
    int row0 = blockIdx.x * 64;

    for (int i = tid; i < 64 * 64; i += 256) W1s[i >> 6][i & 63] = W1[i];
    if (tid < 64) { b0s[tid] = b0[tid]; b1s[tid] = b1[tid]; }

    float acc[4][4] = {};
    int lr = tid >> 2;            // x tile row 0..63
    int lq = tid & 3;             // float4 slot within 16-wide k chunk
    bool rowok = (row0 + lr) < N;
    const float4* xrow = (const float4*)(x + (size_t)(row0 + lr) * FIN);
    int wr = tid >> 4;            // W0 chunk row 0..15
    int wq = tid & 15;            // W0 float4 col slot 0..15

    for (int k0 = 0; k0 < FIN; k0 += 16) {
        float4 xa = rowok ? xrow[(k0 >> 2) + lq] : make_float4(0.f, 0.f, 0.f, 0.f);
        As[lr][4 * lq + 0] = xa.x; As[lr][4 * lq + 1] = xa.y;
        As[lr][4 * lq + 2] = xa.z; As[lr][4 * lq + 3] = xa.w;
        float4 wb = *(const float4*)(W0 + (size_t)(k0 + wr) * HD + 4 * wq);
        Bs[wr][4 * wq + 0] = wb.x; Bs[wr][4 * wq + 1] = wb.y;
        Bs[wr][4 * wq + 2] = wb.z; Bs[wr][4 * wq + 3] = wb.w;
        __syncthreads();
        #pragma unroll
        for (int kk = 0; kk < 16; kk++) {
            float a0 = As[4 * ty + 0][kk], a1 = As[4 * ty + 1][kk];
            float a2 = As[4 * ty + 2][kk], a3 = As[4 * ty + 3][kk];
            float c0 = Bs[kk][4 * tx + 0], c1 = Bs[kk][4 * tx + 1];
            float c2 = Bs[kk][4 * tx + 2], c3 = Bs[kk][4 * tx + 3];
            acc[0][0] += a0 * c0; acc[0][1] += a0 * c1; acc[0][2] += a0 * c2; acc[0][3] += a0 * c3;
            acc[1][0] += a1 * c0; acc[1][1] += a1 * c1; acc[1][2] += a1 * c2; acc[1][3] += a1 * c3;
            acc[2][0] += a2 * c0; acc[2][1] += a2 * c1; acc[2][2] += a2 * c2; acc[2][3] += a2 * c3;
            acc[3][0] += a3 * c0; acc[3][1] += a3 * c1; acc[3][2] += a3 * c2; acc[3][3] += a3 * c3;
        }
        __syncthreads();
    }

    // bias + relu -> Ts
    #pragma unroll
    for (int i = 0; i < 4; i++)
        #pragma unroll
        for (int j = 0; j < 4; j++) {
            float v = acc[i][j] + b0s[4 * tx + j];
            Ts[4 * ty + i][4 * tx + j] = v > 0.f ? v : 0.f;
        }
    __syncthreads();

    // stage B: h = Ts @ W1 + b1
    float acc2[4][4] = {};
    #pragma unroll 8
    for (int k = 0; k < 64; k++) {
        float a0 = Ts[4 * ty + 0][k], a1 = Ts[4 * ty + 1][k];
        float a2 = Ts[4 * ty + 2][k], a3 = Ts[4 * ty + 3][k];
        float c0 = W1s[k][4 * tx + 0], c1 = W1s[k][4 * tx + 1];
        float c2 = W1s[k][4 * tx + 2], c3 = W1s[k][4 * tx + 3];
        acc2[0][0] += a0 * c0; acc2[0][1] += a0 * c1; acc2[0][2] += a0 * c2; acc2[0][3] += a0 * c3;
        acc2[1][0] += a1 * c0; acc2[1][1] += a1 * c1; acc2[1][2] += a1 * c2; acc2[1][3] += a1 * c3;
        acc2[2][0] += a2 * c0; acc2[2][1] += a2 * c1; acc2[2][2] += a2 * c2; acc2[2][3] += a2 * c3;
        acc2[3][0] += a3 * c0; acc2[3][1] += a3 * c1; acc2[3][2] += a3 * c2; acc2[3][3] += a3 * c3;
    }

    #pragma unroll
    for (int i = 0; i < 4; i++) {
        int row = row0 + 4 * ty + i;
        if (row < N) {
            float4 hv = make_float4(acc2[i][0] + b1s[4 * tx + 0],
                                    acc2[i][1] + b1s[4 * tx + 1],
                                    acc2[i][2] + b1s[4 * tx + 2],
                                    acc2[i][3] + b1s[4 * tx + 3]);
            *(float4*)(g_h  + (size_t)row * HD + 4 * tx) = hv;
            *(float4*)(g_z0 + (size_t)row * HD + 4 * tx) = hv;
        }
    }
}

// ---------------- propagation: one warp per destination node -----------------
// lane handles 2 columns (float2): fully coalesced 256B gathers of z[src].
__global__ __launch_bounds__(256) void prop_kernel(int iter, float* __restrict__ dout,
                                                   int N, int niter)
{
    int warp = (blockIdx.x * blockDim.x + threadIdx.x) >> 5;
    int lane = threadIdx.x & 31;
    if (warp >= N) return;

    const float* zin = (iter & 1) ? g_z1 : g_z0;
    float* zout = (iter == niter - 1) ? dout : ((iter & 1) ? g_z0 : g_z1);

    int start = g_rowptr[warp];
    int end   = g_rowptr[warp + 1];

    float2 acc = make_float2(0.f, 0.f);
    for (int e0 = start; e0 < end; e0 += 32) {
        int e = e0 + lane;
        int   s = 0;
        float w = 0.f;
        if (e < end) { s = g_src[e]; w = g_w[e]; }
        int m = min(32, end - e0);
        for (int j = 0; j < m; j++) {
            int   sj = __shfl_sync(0xffffffffu, s, j);
            float wj = __shfl_sync(0xffffffffu, w, j);
            float2 v = *(const float2*)(zin + (size_t)sj * HD + 2 * lane);
            acc.x += wj * v.x;
            acc.y += wj * v.y;
        }
    }

    float2 hh = *(const float2*)(g_h + (size_t)warp * HD + 2 * lane);
    float2 o;
    o.x = (1.0f - ALPHAF) * acc.x + ALPHAF * hh.x;
    o.y = (1.0f - ALPHAF) * acc.y + ALPHAF * hh.y;
    *(float2*)(zout + (size_t)warp * HD + 2 * lane) = o;
}

// ---------------- launcher ----------------------------------------------------
extern "C" void kernel_launch(void* const* d_in, const int* in_sizes, int n_in,
                              void* d_out, int out_size)
{
    const float* x  = (const float*)d_in[0];
    const int*   ei = (const int*)  d_in[1];
    const float* ew = (const float*)d_in[2];
    const float* W0 = (const float*)d_in[3];
    const float* b0 = (const float*)d_in[4];
    const float* W1 = (const float*)d_in[5];
    const float* b1 = (const float*)d_in[6];
    float* out = (float*)d_out;

    int N = in_sizes[0] / FIN;
    int E = in_sizes[2];
    int total = E + N;

    int tpb = 256;
    int nblk = (N + tpb - 1) / tpb;
    int eblk = (total + tpb - 1) / tpb;
    if (eblk > 4096) eblk = 4096;

    zero_kernel<<<nblk, tpb>>>(N);
    degcnt_kernel<<<eblk, tpb>>>(ei, ew, E, N);
    dinv_kernel<<<nblk, tpb>>>(N);
    scan_kernel<<<1, 1024>>>(N, total);
    scatter_kernel<<<eblk, tpb>>>(ei, ew, E, N);
    mlp_kernel<<<(N + 63) / 64, 256>>>(x, W0, b0, W1, b1, N);

    int pblk = (N * 32 + tpb - 1) / tpb;
    for (int it = 0; it < NITER; it++)
        prop_kernel<<<pblk, tpb>>>(it, out, N, NITER);
}

// round 2
// speedup vs baseline: 1.1149x; 1.1149x over previous
#include <cuda_runtime.h>
#include <cuda_bf16.h>

#define NMAX 100000
#define EMAX 3300000   // E + N self loops
#define FIN 512
#define HD  64
#define NITER 10
#define ALPHAF 0.1f
#define SCANB 1024
#define MAXBLK 128     // ceil(NMAX/SCANB) = 98

// ---------------- scratch (device globals; no allocation allowed) ------------
__device__ float g_h[NMAX * HD];        // MLP output (teleport term)
__device__ float g_z0[NMAX * HD];       // ping
__device__ float g_z1[NMAX * HD];       // pong
__device__ float g_deg[NMAX];           // degree -> dinv (in place)
__device__ int   g_cnt[NMAX];           // in-degree histogram (by col)
__device__ int   g_rowptr[NMAX + 1];    // CSR row pointer (by destination)
__device__ int   g_cursor[NMAX];        // scatter cursors
__device__ int2  g_edge[EMAX];          // CSR: {src, weight-bits} packed
__device__ int   g_bsum[MAXBLK];        // block sums for scan

// ---------------- preprocessing kernels --------------------------------------

__global__ void zero_kernel(int N) {
    int i = blockIdx.x * blockDim.x + threadIdx.x;
    int stride = gridDim.x * blockDim.x;
    for (; i < N; i += stride) { g_deg[i] = 0.0f; g_cnt[i] = 0; }
}

__global__ void degcnt_kernel(const int* __restrict__ ei,
                              const float* __restrict__ ew, int E, int N) {
    int total = E + N;
    int i = blockIdx.x * blockDim.x + threadIdx.x;
    int stride = gridDim.x * blockDim.x;
    for (; i < total; i += stride) {
        int r, c; float w;
        if (i < E) { r = ei[i]; c = ei[E + i]; w = ew[i]; }
        else       { r = c = i - E; w = 1.0f; }
        atomicAdd(&g_deg[r], w);
        atomicAdd(&g_cnt[c], 1);
    }
}

__global__ void dinv_kernel(int N) {
    int i = blockIdx.x * blockDim.x + threadIdx.x;
    int stride = gridDim.x * blockDim.x;
    for (; i < N; i += stride) {
        float d = g_deg[i];
        g_deg[i] = (d > 0.0f) ? rsqrtf(d) : 0.0f;
    }
}

// ---- 3-phase parallel exclusive scan of g_cnt -> g_rowptr --------------------
__global__ void scan1_kernel(int N) {
    __shared__ int sdata[SCANB];
    int tid = threadIdx.x;
    int i = blockIdx.x * SCANB + tid;
    int v = (i < N) ? g_cnt[i] : 0;
    sdata[tid] = v;
    __syncthreads();
    #pragma unroll
    for (int off = 1; off < SCANB; off <<= 1) {
        int t = (tid >= off) ? sdata[tid - off] : 0;
        __syncthreads();
        sdata[tid] += t;
        __syncthreads();
    }
    if (i < N) g_rowptr[i] = sdata[tid] - v;     // exclusive within block
    if (tid == SCANB - 1) g_bsum[blockIdx.x] = sdata[tid];
}

__global__ void scan2_kernel(int nblk) {
    // single block, nblk <= MAXBLK <= 128
    __shared__ int sdata[MAXBLK];
    int tid = threadIdx.x;
    int v = (tid < nblk) ? g_bsum[tid] : 0;
    sdata[tid] = v;
    __syncthreads();
    #pragma unroll
    for (int off = 1; off < MAXBLK; off <<= 1) {
        int t = (tid >= off) ? sdata[tid - off] : 0;
        __syncthreads();
        sdata[tid] += t;
        __syncthreads();
    }
    if (tid < nblk) g_bsum[tid] = sdata[tid] - v;  // exclusive
}

__global__ void scan3_kernel(int N, int total) {
    int tid = threadIdx.x;
    int i = blockIdx.x * SCANB + tid;
    if (i < N) {
        int r = g_rowptr[i] + g_bsum[blockIdx.x];
        g_rowptr[i] = r;
        g_cursor[i] = r;
    }
    if (i == N - 1) g_rowptr[N] = total;
}

__global__ void scatter_kernel(const int* __restrict__ ei,
                               const float* __restrict__ ew, int E, int N) {
    int total = E + N;
    int i = blockIdx.x * blockDim.x + threadIdx.x;
    int stride = gridDim.x * blockDim.x;
    for (; i < total; i += stride) {
        int r, c; float w;
        if (i < E) { r = ei[i]; c = ei[E + i]; w = ew[i]; }
        else       { r = c = i - E; w = 1.0f; }
        float wn = g_deg[r] * w * g_deg[c];   // g_deg holds dinv now
        int pos = atomicAdd(&g_cursor[c], 1);
        g_edge[pos] = make_int2(r, __float_as_int(wn));
    }
}

// ---------------- MLP: h = relu(x@W0+b0)@W1+b1, also seeds z0=h --------------
__global__ __launch_bounds__(256) void mlp_kernel(
    const float* __restrict__ x,  const float* __restrict__ W0,
    const float* __restrict__ b0, const float* __restrict__ W1,
    const float* __restrict__ b1, int N)
{
    __shared__ float As[64][17];
    __shared__ float Bs[16][64];
    __shared__ float Ts[64][65];
    __shared__ float W1s[64][64];
    __shared__ float b0s[64];
    __shared__ float b1s[64];

    int tid = threadIdx.x;
    int tx = tid & 15, ty = tid >> 4;
    int row0 = blockIdx.x * 64;

    for (int i = tid; i < 64 * 64; i += 256) W1s[i >> 6][i & 63] = W1[i];
    if (tid < 64) { b0s[tid] = b0[tid]; b1s[tid] = b1[tid]; }

    float acc[4][4] = {};
    int lr = tid >> 2;
    int lq = tid & 3;
    bool rowok = (row0 + lr) < N;
    const float4* xrow = (const float4*)(x + (size_t)(row0 + lr) * FIN);
    int wr = tid >> 4;
    int wq = tid & 15;

    for (int k0 = 0; k0 < FIN; k0 += 16) {
        float4 xa = rowok ? xrow[(k0 >> 2) + lq] : make_float4(0.f, 0.f, 0.f, 0.f);
        As[lr][4 * lq + 0] = xa.x; As[lr][4 * lq + 1] = xa.y;
        As[lr][4 * lq + 2] = xa.z; As[lr][4 * lq + 3] = xa.w;
        float4 wb = *(const float4*)(W0 + (size_t)(k0 + wr) * HD + 4 * wq);
        Bs[wr][4 * wq + 0] = wb.x; Bs[wr][4 * wq + 1] = wb.y;
        Bs[wr][4 * wq + 2] = wb.z; Bs[wr][4 * wq + 3] = wb.w;
        __syncthreads();
        #pragma unroll
        for (int kk = 0; kk < 16; kk++) {
            float a0 = As[4 * ty + 0][kk], a1 = As[4 * ty + 1][kk];
            float a2 = As[4 * ty + 2][kk], a3 = As[4 * ty + 3][kk];
            float c0 = Bs[kk][4 * tx + 0], c1 = Bs[kk][4 * tx + 1];
            float c2 = Bs[kk][4 * tx + 2], c3 = Bs[kk][4 * tx + 3];
            acc[0][0] += a0 * c0; acc[0][1] += a0 * c1; acc[0][2] += a0 * c2; acc[0][3] += a0 * c3;
            acc[1][0] += a1 * c0; acc[1][1] += a1 * c1; acc[1][2] += a1 * c2; acc[1][3] += a1 * c3;
            acc[2][0] += a2 * c0; acc[2][1] += a2 * c1; acc[2][2] += a2 * c2; acc[2][3] += a2 * c3;
            acc[3][0] += a3 * c0; acc[3][1] += a3 * c1; acc[3][2] += a3 * c2; acc[3][3] += a3 * c3;
        }
        __syncthreads();
    }

    #pragma unroll
    for (int i = 0; i < 4; i++)
        #pragma unroll
        for (int j = 0; j < 4; j++) {
            float v = acc[i][j] + b0s[4 * tx + j];
            Ts[4 * ty + i][4 * tx + j] = v > 0.f ? v : 0.f;
        }
    __syncthreads();

    float acc2[4][4] = {};
    #pragma unroll 8
    for (int k = 0; k < 64; k++) {
        float a0 = Ts[4 * ty + 0][k], a1 = Ts[4 * ty + 1][k];
        float a2 = Ts[4 * ty + 2][k], a3 = Ts[4 * ty + 3][k];
        float c0 = W1s[k][4 * tx + 0], c1 = W1s[k][4 * tx + 1];
        float c2 = W1s[k][4 * tx + 2], c3 = W1s[k][4 * tx + 3];
        acc2[0][0] += a0 * c0; acc2[0][1] += a0 * c1; acc2[0][2] += a0 * c2; acc2[0][3] += a0 * c3;
        acc2[1][0] += a1 * c0; acc2[1][1] += a1 * c1; acc2[1][2] += a1 * c2; acc2[1][3] += a1 * c3;
        acc2[2][0] += a2 * c0; acc2[2][1] += a2 * c1; acc2[2][2] += a2 * c2; acc2[2][3] += a2 * c3;
        acc2[3][0] += a3 * c0; acc2[3][1] += a3 * c1; acc2[3][2] += a3 * c2; acc2[3][3] += a3 * c3;
    }

    #pragma unroll
    for (int i = 0; i < 4; i++) {
        int row = row0 + 4 * ty + i;
        if (row < N) {
            float4 hv = make_float4(acc2[i][0] + b1s[4 * tx + 0],
                                    acc2[i][1] + b1s[4 * tx + 1],
                                    acc2[i][2] + b1s[4 * tx + 2],
                                    acc2[i][3] + b1s[4 * tx + 3]);
            *(float4*)(g_h  + (size_t)row * HD + 4 * tx) = hv;
            *(float4*)(g_z0 + (size_t)row * HD + 4 * tx) = hv;
        }
    }
}

// ---------------- propagation: half-warp per destination node -----------------
// 16 lanes per node, lane handles 4 columns (float4): 256B coalesced gathers.
__global__ __launch_bounds__(256) void prop_kernel(int iter, float* __restrict__ dout,
                                                   int N, int niter)
{
    int node = (blockIdx.x * blockDim.x + threadIdx.x) >> 4;
    int lane = threadIdx.x & 15;
    if (node >= N) return;

    const float* zin = (iter & 1) ? g_z1 : g_z0;
    float* zout = (iter == niter - 1) ? dout : ((iter & 1) ? g_z0 : g_z1);

    int start = g_rowptr[node];
    int end   = g_rowptr[node + 1];

    float4 acc = make_float4(0.f, 0.f, 0.f, 0.f);
    for (int e0 = start; e0 < end; e0 += 16) {
        int e = e0 + lane;
        int2 ed = make_int2(0, 0);
        if (e < end) ed = g_edge[e];
        int m = min(16, end - e0);
        #pragma unroll 4
        for (int j = 0; j < m; j++) {
            int   sj = __shfl_sync(0xffffffffu, ed.x, j, 16);
            float wj = __int_as_float(__shfl_sync(0xffffffffu, ed.y, j, 16));
            float4 v = *(const float4*)(zin + (size_t)sj * HD + 4 * lane);
            acc.x += wj * v.x;
            acc.y += wj * v.y;
            acc.z += wj * v.z;
            acc.w += wj * v.w;
        }
    }

    float4 hh = *(const float4*)(g_h + (size_t)node * HD + 4 * lane);
    float4 o;
    o.x = (1.0f - ALPHAF) * acc.x + ALPHAF * hh.x;
    o.y = (1.0f - ALPHAF) * acc.y + ALPHAF * hh.y;
    o.z = (1.0f - ALPHAF) * acc.z + ALPHAF * hh.z;
    o.w = (1.0f - ALPHAF) * acc.w + ALPHAF * hh.w;
    *(float4*)(zout + (size_t)node * HD + 4 * lane) = o;
}

// ---------------- launcher ----------------------------------------------------
extern "C" void kernel_launch(void* const* d_in, const int* in_sizes, int n_in,
                              void* d_out, int out_size)
{
    const float* x  = (const float*)d_in[0];
    const int*   ei = (const int*)  d_in[1];
    const float* ew = (const float*)d_in[2];
    const float* W0 = (const float*)d_in[3];
    const float* b0 = (const float*)d_in[4];
    const float* W1 = (const float*)d_in[5];
    const float* b1 = (const float*)d_in[6];
    float* out = (float*)d_out;

    int N = in_sizes[0] / FIN;
    int E = in_sizes[2];
    int total = E + N;

    int tpb = 256;
    int nblk = (N + tpb - 1) / tpb;
    int eblk = (total + tpb - 1) / tpb;
    if (eblk > 4096) eblk = 4096;
    int sblk = (N + SCANB - 1) / SCANB;

    zero_kernel<<<nblk, tpb>>>(N);
    degcnt_kernel<<<eblk, tpb>>>(ei, ew, E, N);
    dinv_kernel<<<nblk, tpb>>>(N);
    scan1_kernel<<<sblk, SCANB>>>(N);
    scan2_kernel<<<1, MAXBLK>>>(sblk);
    scan3_kernel<<<sblk, SCANB>>>(N, total);
    scatter_kernel<<<eblk, tpb>>>(ei, ew, E, N);
    mlp_kernel<<<(N + 63) / 64, 256>>>(x, W0, b0, W1, b1, N);

    int pblk = (N * 16 + tpb - 1) / tpb;
    for (int it = 0; it < NITER; it++)
        prop_kernel<<<pblk, tpb>>>(it, out, N, NITER);
}